// round 7
// baseline (speedup 1.0000x reference)
#include <cuda_runtime.h>
#include <cuda_fp16.h>
#include <cstdint>
#include <cstddef>

// ---------------- problem constants ----------------
#define N_Uc   8192
#define N_Ic   8192
#define D_INc  2048
#define D_Hc   2048
#define N_TOTc (N_Uc + N_Ic)

// ---------------- fp16 scratch (device globals; no allocs allowed) ----------------
__device__ __half g_inputH[(size_t)N_TOTc * D_INc];   // rn(input)  [16384][2048]
__device__ __half g_WH[(size_t)D_Hc * D_INc];         // rn(W)      [2048][2048]
__device__ __half g_adjH[(size_t)N_Uc * N_Ic];        // rn(adj)    [8192][8192]
__device__ __half g_supH[(size_t)N_TOTc * D_Hc];      // rn(support)[16384][2048]

// ---------------- PTX helpers ----------------
__device__ __forceinline__ uint32_t smem_u32(const void* p) {
    uint32_t a;
    asm("{ .reg .u64 t; cvta.to.shared.u64 t, %1; cvt.u32.u64 %0, t; }" : "=r"(a) : "l"(p));
    return a;
}
__device__ __forceinline__ void cp_async16(uint32_t s, const void* g) {
    asm volatile("cp.async.cg.shared.global [%0], [%1], 16;" :: "r"(s), "l"(g));
}
__device__ __forceinline__ void cp_commit() {
    asm volatile("cp.async.commit_group;" ::: "memory");
}
template<int N>
__device__ __forceinline__ void cp_wait() {
    asm volatile("cp.async.wait_group %0;" :: "n"(N) : "memory");
}
__device__ __forceinline__ void ldsm_x4(uint32_t& r0, uint32_t& r1, uint32_t& r2,
                                        uint32_t& r3, uint32_t addr) {
    asm volatile("ldmatrix.sync.aligned.m8n8.x4.shared.b16 {%0,%1,%2,%3}, [%4];"
                 : "=r"(r0), "=r"(r1), "=r"(r2), "=r"(r3) : "r"(addr));
}
__device__ __forceinline__ void ldsm_x4_t(uint32_t& r0, uint32_t& r1, uint32_t& r2,
                                          uint32_t& r3, uint32_t addr) {
    asm volatile("ldmatrix.sync.aligned.m8n8.x4.trans.shared.b16 {%0,%1,%2,%3}, [%4];"
                 : "=r"(r0), "=r"(r1), "=r"(r2), "=r"(r3) : "r"(addr));
}
__device__ __forceinline__ void mma_f16(float d[4], const uint32_t a[4],
                                        const uint32_t b[2], const float c[4]) {
    asm volatile(
        "mma.sync.aligned.m16n8k16.row.col.f32.f16.f16.f32 "
        "{%0,%1,%2,%3}, {%4,%5,%6,%7}, {%8,%9}, {%10,%11,%12,%13};"
        : "=f"(d[0]), "=f"(d[1]), "=f"(d[2]), "=f"(d[3])
        : "r"(a[0]), "r"(a[1]), "r"(a[2]), "r"(a[3]),
          "r"(b[0]), "r"(b[1]),
          "f"(c[0]), "f"(c[1]), "f"(c[2]), "f"(c[3]));
}

// ---------------- GEMM ----------------
//   C[m][n] = epi( sum_k A(m,k)*B(k,n) )
// A(m,k) = A_K_CONTIG ? A[m*lda+k] : A[k*lda+m]   (halves)
// B(k,n) = B_N_CONTIG ? B[k*ldb+n] : B[n*ldb+k]   (halves)
// EPI==0: C (half) [m][ldc] = rn(acc + E[n])      (bias; writes fp16 support)
// EPI==1: C (float)[m][ldc] = acc * E[m]          (degree scale)
// CTA tile 128x128x64, 4 warps (2x2), warp tile 64x64.
// 2-stage cp.async pipeline, 2 CTAs/SM.
#define BMh 128
#define BNh 128
#define BKh 64
#define NSTG 2
#define NTHR 128
// smem row strides (bytes), padded +16 for ldmatrix conflict-freedom (odd multiples of 16):
#define SKC 144     // K-contig rows: 64 halves = 128B -> 144
#define SMC 272     // MN-contig rows: 128 halves = 256B -> 272

#define ASZ_(AK) ((AK) ? BMh * SKC : BKh * SMC)
#define BSZ_(BN) ((BN) ? BKh * SMC : BNh * SKC)
#define STG_(AK, BN) (ASZ_(AK) + BSZ_(BN))

template<bool A_K_CONTIG, bool B_N_CONTIG, int EPI>
__launch_bounds__(NTHR, 2)
__global__ void hgemm(const __half* __restrict__ A, const __half* __restrict__ B,
                      const float* __restrict__ E, void* __restrict__ Cv,
                      int N, int K, int lda, int ldb, int ldc)
{
    constexpr int ASZ = ASZ_(A_K_CONTIG);
    constexpr int STG = STG_(A_K_CONTIG, B_N_CONTIG);
    extern __shared__ __align__(16) char smem[];
    const uint32_t sb = smem_u32(smem);

    const int tid  = threadIdx.x;
    const int lane = tid & 31;
    const int warp = tid >> 5;           // 0..3
    const int wm   = warp >> 1;          // 0..1  (64 rows)
    const int wn   = warp & 1;           // 0..1  (64 cols)
    const int q    = lane >> 3;          // ldmatrix quad 0..3
    const int r    = lane & 7;
    const int g    = lane >> 2;
    const int t    = lane & 3;

    const int m0 = blockIdx.y * BMh;
    const int n0 = blockIdx.x * BNh;

    float acc[4][8][4];
#pragma unroll
    for (int i = 0; i < 4; i++)
#pragma unroll
        for (int j = 0; j < 8; j++)
#pragma unroll
            for (int k = 0; k < 4; k++) acc[i][j][k] = 0.f;

    // -------- per-thread ldmatrix base offsets (bytes, within panel) --------
    uint32_t a_base, b_base;
    if (A_K_CONTIG)
        a_base = (uint32_t)((wm * 64 + r + (q & 1) * 8) * SKC + (q >> 1) * 16);
    else
        a_base = (uint32_t)((r + (q >> 1) * 8) * SMC + (wm * 64 + (q & 1) * 8) * 2);
    if (B_N_CONTIG)
        b_base = (uint32_t)((r + (q & 1) * 8) * SMC + (wn * 64 + (q >> 1) * 8) * 2);
    else
        b_base = (uint32_t)((wn * 64 + r + (q >> 1) * 8) * SKC + (q & 1) * 16);

    // -------- stage fill (cp.async, 16B chunks; 1024 chunks per panel) --------
    auto fill = [&](int s, int kt) {
        const uint32_t ab = sb + (uint32_t)s * STG;
        const uint32_t bb = ab + ASZ;
        const int k0 = kt * BKh;
        if (A_K_CONTIG) {   // 128 rows x 8 chunks
#pragma unroll
            for (int i = 0; i < 8; i++) {
                int ci = tid + i * NTHR, row = ci >> 3, c = ci & 7;
                cp_async16(ab + row * SKC + c * 16,
                           A + (size_t)(m0 + row) * lda + k0 + c * 8);
            }
        } else {            // 64 k-rows x 16 chunks
#pragma unroll
            for (int i = 0; i < 8; i++) {
                int ci = tid + i * NTHR, row = ci >> 4, c = ci & 15;
                cp_async16(ab + row * SMC + c * 16,
                           A + (size_t)(k0 + row) * lda + m0 + c * 8);
            }
        }
        if (B_N_CONTIG) {   // 64 k-rows x 16 chunks
#pragma unroll
            for (int i = 0; i < 8; i++) {
                int ci = tid + i * NTHR, row = ci >> 4, c = ci & 15;
                cp_async16(bb + row * SMC + c * 16,
                           B + (size_t)(k0 + row) * ldb + n0 + c * 8);
            }
        } else {            // 128 n-rows x 8 chunks
#pragma unroll
            for (int i = 0; i < 8; i++) {
                int ci = tid + i * NTHR, row = ci >> 3, c = ci & 7;
                cp_async16(bb + row * SKC + c * 16,
                           B + (size_t)(n0 + row) * ldb + k0 + c * 8);
            }
        }
        cp_commit();
    };

    const int T = K / BKh;
    fill(0, 0);

    int s = 0;
    for (int kt = 0; kt < T; kt++) {
        if (kt + 1 < T) fill(s ^ 1, kt + 1);
        else            cp_commit();
        cp_wait<1>();
        __syncthreads();

        const uint32_t ab = sb + (uint32_t)s * STG;
        const uint32_t bb = ab + ASZ;
        const uint32_t aa = ab + a_base;
        const uint32_t ba = bb + b_base;

#pragma unroll
        for (int ks = 0; ks < 4; ks++) {   // four k16 steps per stage
            const uint32_t ak = A_K_CONTIG ? (aa + ks * 32) : (aa + ks * 16 * SMC);
            const uint32_t bk = B_N_CONTIG ? (ba + ks * 16 * SMC) : (ba + ks * 32);

            uint32_t af[4][4];
#pragma unroll
            for (int mt = 0; mt < 4; mt++) {
                const uint32_t addr = A_K_CONTIG ? (ak + mt * 16 * SKC) : (ak + mt * 32);
                if (A_K_CONTIG) ldsm_x4  (af[mt][0], af[mt][1], af[mt][2], af[mt][3], addr);
                else            ldsm_x4_t(af[mt][0], af[mt][1], af[mt][2], af[mt][3], addr);
            }
            uint32_t bf[8][2];
#pragma unroll
            for (int h = 0; h < 4; h++) {  // 4 x4 loads cover 8 n-tiles (n64)
                const uint32_t addr = B_N_CONTIG ? (bk + h * 32) : (bk + h * 16 * SKC);
                if (B_N_CONTIG) ldsm_x4_t(bf[2*h][0], bf[2*h][1], bf[2*h+1][0], bf[2*h+1][1], addr);
                else            ldsm_x4  (bf[2*h][0], bf[2*h][1], bf[2*h+1][0], bf[2*h+1][1], addr);
            }
#pragma unroll
            for (int mt = 0; mt < 4; mt++)
#pragma unroll
                for (int nt = 0; nt < 8; nt++)
                    mma_f16(acc[mt][nt], af[mt], bf[nt], acc[mt][nt]);
        }
        __syncthreads();
        s ^= 1;
    }

    // -------- epilogue --------
#pragma unroll
    for (int mt = 0; mt < 4; mt++) {
        const int mr0 = m0 + wm * 64 + mt * 16 + g;
        const int mr1 = mr0 + 8;
        float s0 = 1.f, s1 = 1.f;
        if (EPI == 1) { s0 = E[mr0]; s1 = E[mr1]; }
#pragma unroll
        for (int nt = 0; nt < 8; nt++) {
            const int nc = n0 + wn * 64 + nt * 8 + 2 * t;
            if (EPI == 0) {
                __half* C = (__half*)Cv;
                const float bx = E[nc], by = E[nc + 1];
                *reinterpret_cast<__half2*>(&C[(size_t)mr0 * ldc + nc]) =
                    __floats2half2_rn(acc[mt][nt][0] + bx, acc[mt][nt][1] + by);
                *reinterpret_cast<__half2*>(&C[(size_t)mr1 * ldc + nc]) =
                    __floats2half2_rn(acc[mt][nt][2] + bx, acc[mt][nt][3] + by);
            } else {
                float* C = (float*)Cv;
                float2 v0 = make_float2(acc[mt][nt][0] * s0, acc[mt][nt][1] * s0);
                float2 v1 = make_float2(acc[mt][nt][2] * s1, acc[mt][nt][3] * s1);
                *reinterpret_cast<float2*>(&C[(size_t)mr0 * ldc + nc]) = v0;
                *reinterpret_cast<float2*>(&C[(size_t)mr1 * ldc + nc]) = v1;
            }
        }
    }
}

// ---------------- fp32 -> fp16 pre-pass ----------------
__global__ void f32_to_f16(const float* __restrict__ src, __half* __restrict__ dst) {
    size_t i = ((size_t)blockIdx.x * blockDim.x + threadIdx.x) * 8;
    float4 v0 = *reinterpret_cast<const float4*>(src + i);
    float4 v1 = *reinterpret_cast<const float4*>(src + i + 4);
    __half2 h0 = __floats2half2_rn(v0.x, v0.y);
    __half2 h1 = __floats2half2_rn(v0.z, v0.w);
    __half2 h2 = __floats2half2_rn(v1.x, v1.y);
    __half2 h3 = __floats2half2_rn(v1.z, v1.w);
    uint4 u;
    u.x = *reinterpret_cast<uint32_t*>(&h0);
    u.y = *reinterpret_cast<uint32_t*>(&h1);
    u.z = *reinterpret_cast<uint32_t*>(&h2);
    u.w = *reinterpret_cast<uint32_t*>(&h3);
    *reinterpret_cast<uint4*>(dst + i) = u;
}

// ---------------- launch ----------------
extern "C" void kernel_launch(void* const* d_in, const int* in_sizes, int n_in,
                              void* d_out, int out_size)
{
    const float* input  = (const float*)d_in[0];
    const float* adj    = (const float*)d_in[1];
    const float* degree = (const float*)d_in[2];
    const float* W      = (const float*)d_in[3];
    const float* b      = (const float*)d_in[4];
    float* out = (float*)d_out;

    __half *inputH, *WH, *adjH, *supH;
    cudaGetSymbolAddress((void**)&inputH, g_inputH);
    cudaGetSymbolAddress((void**)&WH, g_WH);
    cudaGetSymbolAddress((void**)&adjH, g_adjH);
    cudaGetSymbolAddress((void**)&supH, g_supH);

    constexpr int SM1 = NSTG * STG_(1, 0);   // 2 * 36864 = 73728
    constexpr int SM2 = NSTG * STG_(1, 1);   // 2 * 35840 = 71680
    constexpr int SM3 = NSTG * STG_(0, 1);   // 2 * 34816 = 69632
    cudaFuncSetAttribute(hgemm<true, false, 0>, cudaFuncAttributeMaxDynamicSharedMemorySize, SM1);
    cudaFuncSetAttribute(hgemm<true, true, 1>,  cudaFuncAttributeMaxDynamicSharedMemorySize, SM2);
    cudaFuncSetAttribute(hgemm<false, true, 1>, cudaFuncAttributeMaxDynamicSharedMemorySize, SM3);

    // pre-passes: RN-round everything to fp16 once
    f32_to_f16<<<(size_t)N_TOTc * D_INc / (8 * 256), 256>>>(input, inputH);
    f32_to_f16<<<(size_t)D_Hc * D_INc / (8 * 256), 256>>>(W, WH);
    f32_to_f16<<<(size_t)N_Uc * N_Ic / (8 * 256), 256>>>(adj, adjH);

    // GEMM1: supH = rn( input @ W^T + b )  (M=16384, N=2048, K=2048)
    {
        dim3 grid(D_Hc / BNh, N_TOTc / BMh);
        hgemm<true, false, 0><<<grid, NTHR, SM1>>>(
            inputH, WH, b, supH, D_Hc, D_INc, D_INc, D_INc, D_Hc);
    }
    // GEMM2: out_u = deg_u * (adj @ sup_i)
    {
        dim3 grid(D_Hc / BNh, N_Uc / BMh);
        hgemm<true, true, 1><<<grid, NTHR, SM2>>>(
            adjH, supH + (size_t)N_Uc * D_Hc, degree, out,
            D_Hc, N_Ic, N_Ic, D_Hc, D_Hc);
    }
    // GEMM3: out_i = deg_i * (adj^T @ sup_u)
    {
        dim3 grid(D_Hc / BNh, N_Ic / BMh);
        hgemm<false, true, 1><<<grid, NTHR, SM3>>>(
            adjH, supH, degree + N_Uc, out + (size_t)N_Uc * D_Hc,
            D_Hc, N_Uc, N_Ic, D_Hc, D_Hc);
    }
}

// round 8
// speedup vs baseline: 1.1049x; 1.1049x over previous
#include <cuda_runtime.h>
#include <cuda_fp16.h>
#include <cstdint>
#include <cstddef>

// ---------------- problem constants ----------------
#define N_Uc   8192
#define N_Ic   8192
#define D_INc  2048
#define D_Hc   2048
#define N_TOTc (N_Uc + N_Ic)

// ---------------- fp16 scratch (device globals; no allocs allowed) ----------------
__device__ __half g_inputH[(size_t)N_TOTc * D_INc];   // rn(input)  [16384][2048]
__device__ __half g_WH[(size_t)D_Hc * D_INc];         // rn(W)      [2048][2048]
__device__ __half g_adjH[(size_t)N_Uc * N_Ic];        // rn(adj)    [8192][8192]
__device__ __half g_supH[(size_t)N_TOTc * D_Hc];      // rn(support)[16384][2048]

// ---------------- PTX helpers ----------------
__device__ __forceinline__ uint32_t smem_u32(const void* p) {
    uint32_t a;
    asm("{ .reg .u64 t; cvta.to.shared.u64 t, %1; cvt.u32.u64 %0, t; }" : "=r"(a) : "l"(p));
    return a;
}
__device__ __forceinline__ void cp_async16(uint32_t s, const void* g) {
    asm volatile("cp.async.cg.shared.global [%0], [%1], 16;" :: "r"(s), "l"(g));
}
__device__ __forceinline__ void cp_commit() {
    asm volatile("cp.async.commit_group;" ::: "memory");
}
template<int N>
__device__ __forceinline__ void cp_wait() {
    asm volatile("cp.async.wait_group %0;" :: "n"(N) : "memory");
}
__device__ __forceinline__ void ldsm_x4(uint32_t& r0, uint32_t& r1, uint32_t& r2,
                                        uint32_t& r3, uint32_t addr) {
    asm volatile("ldmatrix.sync.aligned.m8n8.x4.shared.b16 {%0,%1,%2,%3}, [%4];"
                 : "=r"(r0), "=r"(r1), "=r"(r2), "=r"(r3) : "r"(addr));
}
__device__ __forceinline__ void ldsm_x4_t(uint32_t& r0, uint32_t& r1, uint32_t& r2,
                                          uint32_t& r3, uint32_t addr) {
    asm volatile("ldmatrix.sync.aligned.m8n8.x4.trans.shared.b16 {%0,%1,%2,%3}, [%4];"
                 : "=r"(r0), "=r"(r1), "=r"(r2), "=r"(r3) : "r"(addr));
}
__device__ __forceinline__ void mma_f16(float d[4], const uint32_t a[4],
                                        const uint32_t b[2], const float c[4]) {
    asm volatile(
        "mma.sync.aligned.m16n8k16.row.col.f32.f16.f16.f32 "
        "{%0,%1,%2,%3}, {%4,%5,%6,%7}, {%8,%9}, {%10,%11,%12,%13};"
        : "=f"(d[0]), "=f"(d[1]), "=f"(d[2]), "=f"(d[3])
        : "r"(a[0]), "r"(a[1]), "r"(a[2]), "r"(a[3]),
          "r"(b[0]), "r"(b[1]),
          "f"(c[0]), "f"(c[1]), "f"(c[2]), "f"(c[3]));
}

// ============================================================================
// Kernel A (for GEMM1; L2-resident B): CTA 128x128x64, 4 warps (2x2),
// warp tile 64x64, 2-stage. A K-contig, B [n][k] K-contig, bias epilogue,
// fp16 output. (Round-7 config, measured 392us / tensor 58%.)
// ============================================================================
#define BMa 128
#define BNa 128
#define BKa 64
#define SKCa 144    // K-contig rows: 64 halves = 128B -> 144
#define ASZa (BMa * SKCa)
#define BSZa (BNa * SKCa)
#define STGa (ASZa + BSZa)
#define SMEM_A_TOTAL (2 * STGa)   // 73728

__launch_bounds__(128, 2)
__global__ void hgemmA(const __half* __restrict__ A, const __half* __restrict__ B,
                       const float* __restrict__ E, __half* __restrict__ C,
                       int K, int lda, int ldb, int ldc)
{
    extern __shared__ __align__(16) char smem[];
    const uint32_t sb = smem_u32(smem);

    const int tid  = threadIdx.x;
    const int lane = tid & 31;
    const int warp = tid >> 5;           // 0..3
    const int wm   = warp >> 1;          // 0..1  (64 rows)
    const int wn   = warp & 1;           // 0..1  (64 cols)
    const int q    = lane >> 3;
    const int r    = lane & 7;
    const int g    = lane >> 2;
    const int t    = lane & 3;

    const int m0 = blockIdx.y * BMa;
    const int n0 = blockIdx.x * BNa;

    float acc[4][8][4];
#pragma unroll
    for (int i = 0; i < 4; i++)
#pragma unroll
        for (int j = 0; j < 8; j++)
#pragma unroll
            for (int k = 0; k < 4; k++) acc[i][j][k] = 0.f;

    const uint32_t a_base = (uint32_t)((wm * 64 + r + (q & 1) * 8) * SKCa + (q >> 1) * 16);
    const uint32_t b_base = (uint32_t)((wn * 64 + r + (q >> 1) * 8) * SKCa + (q & 1) * 16);

    auto fill = [&](int s, int kt) {
        const uint32_t ab = sb + (uint32_t)s * STGa;
        const uint32_t bb = ab + ASZa;
        const int k0 = kt * BKa;
#pragma unroll
        for (int i = 0; i < 8; i++) {    // A: 128 rows x 8 chunks
            int ci = tid + i * 128, row = ci >> 3, c = ci & 7;
            cp_async16(ab + row * SKCa + c * 16,
                       A + (size_t)(m0 + row) * lda + k0 + c * 8);
        }
#pragma unroll
        for (int i = 0; i < 8; i++) {    // B: 128 n-rows x 8 chunks (K-contig)
            int ci = tid + i * 128, row = ci >> 3, c = ci & 7;
            cp_async16(bb + row * SKCa + c * 16,
                       B + (size_t)(n0 + row) * ldb + k0 + c * 8);
        }
        cp_commit();
    };

    const int T = K / BKa;
    fill(0, 0);

    int s = 0;
    for (int kt = 0; kt < T; kt++) {
        if (kt + 1 < T) fill(s ^ 1, kt + 1);
        else            cp_commit();
        cp_wait<1>();
        __syncthreads();

        const uint32_t aa = sb + (uint32_t)s * STGa + a_base;
        const uint32_t ba = sb + (uint32_t)s * STGa + ASZa + b_base;

#pragma unroll
        for (int ks = 0; ks < 4; ks++) {
            const uint32_t ak = aa + ks * 32;
            const uint32_t bk = ba + ks * 32;
            uint32_t af[4][4];
#pragma unroll
            for (int mt = 0; mt < 4; mt++)
                ldsm_x4(af[mt][0], af[mt][1], af[mt][2], af[mt][3], ak + mt * 16 * SKCa);
            uint32_t bf[8][2];
#pragma unroll
            for (int h = 0; h < 4; h++)
                ldsm_x4(bf[2*h][0], bf[2*h][1], bf[2*h+1][0], bf[2*h+1][1], bk + h * 16 * SKCa);
#pragma unroll
            for (int mt = 0; mt < 4; mt++)
#pragma unroll
                for (int nt = 0; nt < 8; nt++)
                    mma_f16(acc[mt][nt], af[mt], bf[nt], acc[mt][nt]);
        }
        __syncthreads();
        s ^= 1;
    }

#pragma unroll
    for (int mt = 0; mt < 4; mt++) {
        const int mr0 = m0 + wm * 64 + mt * 16 + g;
        const int mr1 = mr0 + 8;
#pragma unroll
        for (int nt = 0; nt < 8; nt++) {
            const int nc = n0 + wn * 64 + nt * 8 + 2 * t;
            const float bx = E[nc], by = E[nc + 1];
            *reinterpret_cast<__half2*>(&C[(size_t)mr0 * ldc + nc]) =
                __floats2half2_rn(acc[mt][nt][0] + bx, acc[mt][nt][1] + by);
            *reinterpret_cast<__half2*>(&C[(size_t)mr1 * ldc + nc]) =
                __floats2half2_rn(acc[mt][nt][2] + bx, acc[mt][nt][3] + by);
        }
    }
}

// ============================================================================
// Kernel B (for GEMM2/3; DRAM-streaming A): CTA 128x128x32, 8 warps (2x4),
// warp tile 64x32, 4-stage, 2 CTAs/SM, degree-scale epilogue, fp32 output.
// (Round-6 config, measured ~370 TF/s on these GEMMs.)
// ============================================================================
#define BMb 128
#define BNb 128
#define BKb 32
#define NSTGb 4
#define SKCb 80     // K-contig rows: 32 halves = 64B -> 80
#define SMCb 272    // M-contig rows: 128 halves = 256B -> 272

#define ASZb_(AK) ((AK) ? BMb * SKCb : BKb * SMCb)
#define BSZb (BKb * SMCb)
#define STGb_(AK) (ASZb_(AK) + BSZb)

template<bool A_K_CONTIG>
__launch_bounds__(256, 2)
__global__ void hgemmB(const __half* __restrict__ A, const __half* __restrict__ B,
                       const float* __restrict__ E, float* __restrict__ C,
                       int K, int lda, int ldb, int ldc)
{
    constexpr int ASZ = ASZb_(A_K_CONTIG);
    constexpr int STG = STGb_(A_K_CONTIG);
    extern __shared__ __align__(16) char smem[];
    const uint32_t sb = smem_u32(smem);

    const int tid  = threadIdx.x;
    const int lane = tid & 31;
    const int warp = tid >> 5;
    const int wm   = warp >> 2;          // 0..1
    const int wn   = warp & 3;           // 0..3
    const int q    = lane >> 3;
    const int r    = lane & 7;
    const int g    = lane >> 2;
    const int t    = lane & 3;

    const int m0 = blockIdx.y * BMb;
    const int n0 = blockIdx.x * BNb;

    float acc[4][4][4];
#pragma unroll
    for (int i = 0; i < 4; i++)
#pragma unroll
        for (int j = 0; j < 4; j++)
#pragma unroll
            for (int k = 0; k < 4; k++) acc[i][j][k] = 0.f;

    uint32_t a_base;
    if (A_K_CONTIG)
        a_base = (uint32_t)((wm * 64 + r + (q & 1) * 8) * SKCb + (q >> 1) * 16);
    else
        a_base = (uint32_t)((r + (q >> 1) * 8) * SMCb + (wm * 64 + (q & 1) * 8) * 2);
    const uint32_t b_base =
        (uint32_t)((r + (q & 1) * 8) * SMCb + (wn * 32 + (q >> 1) * 8) * 2);

    auto fill = [&](int s, int kt) {
        const uint32_t ab = sb + (uint32_t)s * STG;
        const uint32_t bb = ab + ASZ;
        const int k0 = kt * BKb;
        if (A_K_CONTIG) {   // 128 rows x 4 chunks
#pragma unroll
            for (int i = 0; i < 2; i++) {
                int ci = tid + i * 256, row = ci >> 2, c = ci & 3;
                cp_async16(ab + row * SKCb + c * 16,
                           A + (size_t)(m0 + row) * lda + k0 + c * 8);
            }
        } else {            // 32 k-rows x 16 chunks
#pragma unroll
            for (int i = 0; i < 2; i++) {
                int ci = tid + i * 256, row = ci >> 4, c = ci & 15;
                cp_async16(ab + row * SMCb + c * 16,
                           A + (size_t)(k0 + row) * lda + m0 + c * 8);
            }
        }
        {                   // B: 32 k-rows x 16 chunks (N-contig)
#pragma unroll
            for (int i = 0; i < 2; i++) {
                int ci = tid + i * 256, row = ci >> 4, c = ci & 15;
                cp_async16(bb + row * SMCb + c * 16,
                           B + (size_t)(k0 + row) * ldb + n0 + c * 8);
            }
        }
        cp_commit();
    };

    const int T = K / BKb;
    fill(0, 0);
    fill(1, 1);
    fill(2, 2);

    int s = 0;
    for (int kt = 0; kt < T; kt++) {
        if (kt + 3 < T) {
            int ns = s + 3; if (ns >= NSTGb) ns -= NSTGb;
            fill(ns, kt + 3);
        } else {
            cp_commit();
        }
        cp_wait<3>();
        __syncthreads();

        const uint32_t ab = sb + (uint32_t)s * STG;
        const uint32_t aa = ab + a_base;
        const uint32_t ba = ab + ASZ + b_base;

#pragma unroll
        for (int ks = 0; ks < 2; ks++) {
            const uint32_t ak = A_K_CONTIG ? (aa + ks * 32) : (aa + ks * 16 * SMCb);
            const uint32_t bk = ba + ks * 16 * SMCb;

            uint32_t af[4][4];
#pragma unroll
            for (int mt = 0; mt < 4; mt++) {
                const uint32_t addr = A_K_CONTIG ? (ak + mt * 16 * SKCb) : (ak + mt * 32);
                if (A_K_CONTIG) ldsm_x4  (af[mt][0], af[mt][1], af[mt][2], af[mt][3], addr);
                else            ldsm_x4_t(af[mt][0], af[mt][1], af[mt][2], af[mt][3], addr);
            }
            uint32_t bf[4][2];
#pragma unroll
            for (int h = 0; h < 2; h++)
                ldsm_x4_t(bf[2*h][0], bf[2*h][1], bf[2*h+1][0], bf[2*h+1][1], bk + h * 32);
#pragma unroll
            for (int mt = 0; mt < 4; mt++)
#pragma unroll
                for (int nt = 0; nt < 4; nt++)
                    mma_f16(acc[mt][nt], af[mt], bf[nt], acc[mt][nt]);
        }
        __syncthreads();
        if (++s == NSTGb) s = 0;
    }

#pragma unroll
    for (int mt = 0; mt < 4; mt++) {
        const int mr0 = m0 + wm * 64 + mt * 16 + g;
        const int mr1 = mr0 + 8;
        const float s0 = E[mr0], s1 = E[mr1];
#pragma unroll
        for (int nt = 0; nt < 4; nt++) {
            const int nc = n0 + wn * 32 + nt * 8 + 2 * t;
            float2 v0 = make_float2(acc[mt][nt][0] * s0, acc[mt][nt][1] * s0);
            float2 v1 = make_float2(acc[mt][nt][2] * s1, acc[mt][nt][3] * s1);
            *reinterpret_cast<float2*>(&C[(size_t)mr0 * ldc + nc]) = v0;
            *reinterpret_cast<float2*>(&C[(size_t)mr1 * ldc + nc]) = v1;
        }
    }
}

// ---------------- fp32 -> fp16 pre-pass ----------------
__global__ void f32_to_f16(const float* __restrict__ src, __half* __restrict__ dst) {
    size_t i = ((size_t)blockIdx.x * blockDim.x + threadIdx.x) * 8;
    float4 v0 = *reinterpret_cast<const float4*>(src + i);
    float4 v1 = *reinterpret_cast<const float4*>(src + i + 4);
    __half2 h0 = __floats2half2_rn(v0.x, v0.y);
    __half2 h1 = __floats2half2_rn(v0.z, v0.w);
    __half2 h2 = __floats2half2_rn(v1.x, v1.y);
    __half2 h3 = __floats2half2_rn(v1.z, v1.w);
    uint4 u;
    u.x = *reinterpret_cast<uint32_t*>(&h0);
    u.y = *reinterpret_cast<uint32_t*>(&h1);
    u.z = *reinterpret_cast<uint32_t*>(&h2);
    u.w = *reinterpret_cast<uint32_t*>(&h3);
    *reinterpret_cast<uint4*>(dst + i) = u;
}

// ---------------- launch ----------------
extern "C" void kernel_launch(void* const* d_in, const int* in_sizes, int n_in,
                              void* d_out, int out_size)
{
    const float* input  = (const float*)d_in[0];
    const float* adj    = (const float*)d_in[1];
    const float* degree = (const float*)d_in[2];
    const float* W      = (const float*)d_in[3];
    const float* b      = (const float*)d_in[4];
    float* out = (float*)d_out;

    __half *inputH, *WH, *adjH, *supH;
    cudaGetSymbolAddress((void**)&inputH, g_inputH);
    cudaGetSymbolAddress((void**)&WH, g_WH);
    cudaGetSymbolAddress((void**)&adjH, g_adjH);
    cudaGetSymbolAddress((void**)&supH, g_supH);

    constexpr int SMB_K = NSTGb * STGb_(1);   // 4 * 18944 = 75776
    constexpr int SMB_M = NSTGb * STGb_(0);   // 4 * 17408 = 69632
    cudaFuncSetAttribute(hgemmA, cudaFuncAttributeMaxDynamicSharedMemorySize, SMEM_A_TOTAL);
    cudaFuncSetAttribute(hgemmB<true>,  cudaFuncAttributeMaxDynamicSharedMemorySize, SMB_K);
    cudaFuncSetAttribute(hgemmB<false>, cudaFuncAttributeMaxDynamicSharedMemorySize, SMB_M);

    // pre-passes: RN-round everything to fp16 once
    f32_to_f16<<<(size_t)N_TOTc * D_INc / (8 * 256), 256>>>(input, inputH);
    f32_to_f16<<<(size_t)D_Hc * D_INc / (8 * 256), 256>>>(W, WH);
    f32_to_f16<<<(size_t)N_Uc * N_Ic / (8 * 256), 256>>>(adj, adjH);

    // GEMM1: supH = rn( input @ W^T + b )   — kernel A
    {
        dim3 grid(D_Hc / BNa, N_TOTc / BMa);
        hgemmA<<<grid, 128, SMEM_A_TOTAL>>>(
            inputH, WH, b, supH, D_INc, D_INc, D_INc, D_Hc);
    }
    // GEMM2: out_u = deg_u * (adj @ sup_i)  — kernel B (A K-contig)
    {
        dim3 grid(D_Hc / BNb, N_Uc / BMb);
        hgemmB<true><<<grid, 256, SMB_K>>>(
            adjH, supH + (size_t)N_Uc * D_Hc, degree, out,
            N_Ic, N_Ic, D_Hc, D_Hc);
    }
    // GEMM3: out_i = deg_i * (adj^T @ sup_u) — kernel B (A M-contig)
    {
        dim3 grid(D_Hc / BNb, N_Ic / BMb);
        hgemmB<false><<<grid, 256, SMB_M>>>(
            adjH, supH, degree + N_Uc, out + (size_t)N_Uc * D_Hc,
            N_Uc, N_Ic, D_Hc, D_Hc);
    }
}

// round 9
// speedup vs baseline: 1.1605x; 1.0503x over previous
#include <cuda_runtime.h>
#include <cuda_fp16.h>
#include <cstdint>
#include <cstddef>

// ---------------- problem constants ----------------
#define N_Uc   8192
#define N_Ic   8192
#define D_INc  2048
#define D_Hc   2048
#define N_TOTc (N_Uc + N_Ic)

// ---------------- fp16 scratch (device globals; no allocs allowed) ----------------
__device__ __half g_inputH[(size_t)N_TOTc * D_INc];   // rn(input)  [16384][2048]
__device__ __half g_WH[(size_t)D_Hc * D_INc];         // rn(W)      [2048][2048]
__device__ __half g_adjH[(size_t)N_Uc * N_Ic];        // rn(adj)    [8192][8192]
__device__ __half g_supH[(size_t)N_TOTc * D_Hc];      // rn(support)[16384][2048]

// ---------------- PTX helpers ----------------
__device__ __forceinline__ uint32_t smem_u32(const void* p) {
    uint32_t a;
    asm("{ .reg .u64 t; cvta.to.shared.u64 t, %1; cvt.u32.u64 %0, t; }" : "=r"(a) : "l"(p));
    return a;
}
__device__ __forceinline__ void cp_async16(uint32_t s, const void* g) {
    asm volatile("cp.async.cg.shared.global [%0], [%1], 16;" :: "r"(s), "l"(g));
}
__device__ __forceinline__ void cp_commit() {
    asm volatile("cp.async.commit_group;" ::: "memory");
}
template<int N>
__device__ __forceinline__ void cp_wait() {
    asm volatile("cp.async.wait_group %0;" :: "n"(N) : "memory");
}
__device__ __forceinline__ void ldsm_x4(uint32_t& r0, uint32_t& r1, uint32_t& r2,
                                        uint32_t& r3, uint32_t addr) {
    asm volatile("ldmatrix.sync.aligned.m8n8.x4.shared.b16 {%0,%1,%2,%3}, [%4];"
                 : "=r"(r0), "=r"(r1), "=r"(r2), "=r"(r3) : "r"(addr));
}
__device__ __forceinline__ void ldsm_x4_t(uint32_t& r0, uint32_t& r1, uint32_t& r2,
                                          uint32_t& r3, uint32_t addr) {
    asm volatile("ldmatrix.sync.aligned.m8n8.x4.trans.shared.b16 {%0,%1,%2,%3}, [%4];"
                 : "=r"(r0), "=r"(r1), "=r"(r2), "=r"(r3) : "r"(addr));
}
__device__ __forceinline__ void mma_f16(float d[4], const uint32_t a[4],
                                        const uint32_t b[2], const float c[4]) {
    asm volatile(
        "mma.sync.aligned.m16n8k16.row.col.f32.f16.f16.f32 "
        "{%0,%1,%2,%3}, {%4,%5,%6,%7}, {%8,%9}, {%10,%11,%12,%13};"
        : "=f"(d[0]), "=f"(d[1]), "=f"(d[2]), "=f"(d[3])
        : "r"(a[0]), "r"(a[1]), "r"(a[2]), "r"(a[3]),
          "r"(b[0]), "r"(b[1]),
          "f"(c[0]), "f"(c[1]), "f"(c[2]), "f"(c[3]));
}

// ============================================================================
// Kernel A (GEMM1): CTA 128x128x64, 4 warps (2x2), warp 64x64, 3-stage,
// single __syncthreads per iteration, 2 CTAs/SM. A K-contig, B [n][k] K-contig.
// ============================================================================
#define BMa 128
#define BNa 128
#define BKa 64
#define NSTGa 3
#define SKCa 144    // 64 halves = 128B -> 144
#define ASZa (BMa * SKCa)
#define BSZa (BNa * SKCa)
#define STGa (ASZa + BSZa)
#define SMEM_A_TOTAL (NSTGa * STGa)   // 110592

__launch_bounds__(128, 2)
__global__ void hgemmA(const __half* __restrict__ A, const __half* __restrict__ B,
                       const float* __restrict__ E, __half* __restrict__ C,
                       int K, int lda, int ldb, int ldc)
{
    extern __shared__ __align__(16) char smem[];
    const uint32_t sb = smem_u32(smem);

    const int tid  = threadIdx.x;
    const int lane = tid & 31;
    const int warp = tid >> 5;
    const int wm   = warp >> 1;
    const int wn   = warp & 1;
    const int q    = lane >> 3;
    const int r    = lane & 7;
    const int g    = lane >> 2;
    const int t    = lane & 3;

    const int m0 = blockIdx.y * BMa;
    const int n0 = blockIdx.x * BNa;

    float acc[4][8][4];
#pragma unroll
    for (int i = 0; i < 4; i++)
#pragma unroll
        for (int j = 0; j < 8; j++)
#pragma unroll
            for (int k = 0; k < 4; k++) acc[i][j][k] = 0.f;

    const uint32_t a_base = (uint32_t)((wm * 64 + r + (q & 1) * 8) * SKCa + (q >> 1) * 16);
    const uint32_t b_base = (uint32_t)((wn * 64 + r + (q >> 1) * 8) * SKCa + (q & 1) * 16);

    auto fill = [&](int s, int kt) {
        const uint32_t ab = sb + (uint32_t)s * STGa;
        const uint32_t bb = ab + ASZa;
        const int k0 = kt * BKa;
#pragma unroll
        for (int i = 0; i < 8; i++) {
            int ci = tid + i * 128, row = ci >> 3, c = ci & 7;
            cp_async16(ab + row * SKCa + c * 16,
                       A + (size_t)(m0 + row) * lda + k0 + c * 8);
        }
#pragma unroll
        for (int i = 0; i < 8; i++) {
            int ci = tid + i * 128, row = ci >> 3, c = ci & 7;
            cp_async16(bb + row * SKCa + c * 16,
                       B + (size_t)(n0 + row) * ldb + k0 + c * 8);
        }
        cp_commit();
    };

    const int T = K / BKa;
    fill(0, 0);
    fill(1, 1);

    int s = 0;
    for (int kt = 0; kt < T; kt++) {
        cp_wait<1>();
        __syncthreads();
        if (kt + 2 < T) {
            int ns = s + 2; if (ns >= NSTGa) ns -= NSTGa;
            fill(ns, kt + 2);
        } else {
            cp_commit();
        }

        const uint32_t aa = sb + (uint32_t)s * STGa + a_base;
        const uint32_t ba = sb + (uint32_t)s * STGa + ASZa + b_base;
#pragma unroll
        for (int ks = 0; ks < 4; ks++) {
            const uint32_t ak = aa + ks * 32;
            const uint32_t bk = ba + ks * 32;
            uint32_t af[4][4];
#pragma unroll
            for (int mt = 0; mt < 4; mt++)
                ldsm_x4(af[mt][0], af[mt][1], af[mt][2], af[mt][3], ak + mt * 16 * SKCa);
            uint32_t bf[8][2];
#pragma unroll
            for (int h = 0; h < 4; h++)
                ldsm_x4(bf[2*h][0], bf[2*h][1], bf[2*h+1][0], bf[2*h+1][1], bk + h * 16 * SKCa);
#pragma unroll
            for (int mt = 0; mt < 4; mt++)
#pragma unroll
                for (int nt = 0; nt < 8; nt++)
                    mma_f16(acc[mt][nt], af[mt], bf[nt], acc[mt][nt]);
        }
        if (++s == NSTGa) s = 0;
    }
    // last iteration has no trailing sync; epilogue only reads registers.

#pragma unroll
    for (int mt = 0; mt < 4; mt++) {
        const int mr0 = m0 + wm * 64 + mt * 16 + g;
        const int mr1 = mr0 + 8;
#pragma unroll
        for (int nt = 0; nt < 8; nt++) {
            const int nc = n0 + wn * 64 + nt * 8 + 2 * t;
            const float bx = E[nc], by = E[nc + 1];
            *reinterpret_cast<__half2*>(&C[(size_t)mr0 * ldc + nc]) =
                __floats2half2_rn(acc[mt][nt][0] + bx, acc[mt][nt][1] + by);
            *reinterpret_cast<__half2*>(&C[(size_t)mr1 * ldc + nc]) =
                __floats2half2_rn(acc[mt][nt][2] + bx, acc[mt][nt][3] + by);
        }
    }
}

// ============================================================================
// Kernel B (GEMM2+GEMM3 merged): CTA 128x128x64, 8 warps (2x4), warp 64x32,
// 3-stage, single __syncthreads per iteration, 2 CTAs/SM.
// blockIdx.y < 64  -> GEMM2: A=adj[m][k] (K-contig)
// blockIdx.y >= 64 -> GEMM3: A=adj[k][m] (M-contig, ldmatrix.trans)
// ============================================================================
#define BMb 128
#define BNb 128
#define BKb 64
#define NSTGb 3
#define SKCb 144    // K-contig rows: 64 halves = 128B -> 144
#define SMCb 272    // M/N-contig rows: 128 halves = 256B -> 272
#define ASZb 18432  // max(128*144, 64*272) = max(18432, 17408)
#define BSZb (BKb * SMCb)              // 17408
#define STGb (ASZb + BSZb)             // 35840
#define SMEM_B_TOTAL (NSTGb * STGb)    // 107520

template<bool A_K_CONTIG>
__device__ __forceinline__ void gemmB_body(
    const __half* __restrict__ A, const __half* __restrict__ B,
    const float* __restrict__ E, float* __restrict__ C,
    int m0, int n0, uint32_t sb)
{
    const int K   = A_K_CONTIG ? N_Ic : N_Uc;   // 8192 both
    const int lda = A_K_CONTIG ? N_Ic : N_Ic;   // adj row stride
    const int ldb = D_Hc;
    const int ldc = D_Hc;

    const int tid  = threadIdx.x;
    const int lane = tid & 31;
    const int warp = tid >> 5;
    const int wm   = warp >> 2;          // 0..1
    const int wn   = warp & 3;           // 0..3
    const int q    = lane >> 3;
    const int r    = lane & 7;
    const int g    = lane >> 2;
    const int t    = lane & 3;

    float acc[4][4][4];
#pragma unroll
    for (int i = 0; i < 4; i++)
#pragma unroll
        for (int j = 0; j < 4; j++)
#pragma unroll
            for (int k = 0; k < 4; k++) acc[i][j][k] = 0.f;

    uint32_t a_base;
    if (A_K_CONTIG)
        a_base = (uint32_t)((wm * 64 + r + (q & 1) * 8) * SKCb + (q >> 1) * 16);
    else
        a_base = (uint32_t)((r + (q >> 1) * 8) * SMCb + (wm * 64 + (q & 1) * 8) * 2);
    const uint32_t b_base =
        (uint32_t)((r + (q & 1) * 8) * SMCb + (wn * 32 + (q >> 1) * 8) * 2);

    auto fill = [&](int s, int kt) {
        const uint32_t ab = sb + (uint32_t)s * STGb;
        const uint32_t bb = ab + ASZb;
        const int k0 = kt * BKb;
        if (A_K_CONTIG) {   // 128 rows x 8 chunks = 1024
#pragma unroll
            for (int i = 0; i < 4; i++) {
                int ci = tid + i * 256, row = ci >> 3, c = ci & 7;
                cp_async16(ab + row * SKCb + c * 16,
                           A + (size_t)(m0 + row) * lda + k0 + c * 8);
            }
        } else {            // 64 k-rows x 16 chunks = 1024
#pragma unroll
            for (int i = 0; i < 4; i++) {
                int ci = tid + i * 256, row = ci >> 4, c = ci & 15;
                cp_async16(ab + row * SMCb + c * 16,
                           A + (size_t)(k0 + row) * lda + m0 + c * 8);
            }
        }
        {                   // B: 64 k-rows x 16 chunks = 1024
#pragma unroll
            for (int i = 0; i < 4; i++) {
                int ci = tid + i * 256, row = ci >> 4, c = ci & 15;
                cp_async16(bb + row * SMCb + c * 16,
                           B + (size_t)(k0 + row) * ldb + n0 + c * 8);
            }
        }
        cp_commit();
    };

    const int T = K / BKb;
    fill(0, 0);
    fill(1, 1);

    int s = 0;
    for (int kt = 0; kt < T; kt++) {
        cp_wait<1>();
        __syncthreads();
        if (kt + 2 < T) {
            int ns = s + 2; if (ns >= NSTGb) ns -= NSTGb;
            fill(ns, kt + 2);
        } else {
            cp_commit();
        }

        const uint32_t aa = sb + (uint32_t)s * STGb + a_base;
        const uint32_t ba = sb + (uint32_t)s * STGb + ASZb + b_base;
#pragma unroll
        for (int ks = 0; ks < 4; ks++) {
            const uint32_t ak = A_K_CONTIG ? (aa + ks * 32) : (aa + ks * 16 * SMCb);
            const uint32_t bk = ba + ks * 16 * SMCb;

            uint32_t af[4][4];
#pragma unroll
            for (int mt = 0; mt < 4; mt++) {
                const uint32_t addr = A_K_CONTIG ? (ak + mt * 16 * SKCb) : (ak + mt * 32);
                if (A_K_CONTIG) ldsm_x4  (af[mt][0], af[mt][1], af[mt][2], af[mt][3], addr);
                else            ldsm_x4_t(af[mt][0], af[mt][1], af[mt][2], af[mt][3], addr);
            }
            uint32_t bf[4][2];
#pragma unroll
            for (int h = 0; h < 2; h++)
                ldsm_x4_t(bf[2*h][0], bf[2*h][1], bf[2*h+1][0], bf[2*h+1][1], bk + h * 32);
#pragma unroll
            for (int mt = 0; mt < 4; mt++)
#pragma unroll
                for (int nt = 0; nt < 4; nt++)
                    mma_f16(acc[mt][nt], af[mt], bf[nt], acc[mt][nt]);
        }
        if (++s == NSTGb) s = 0;
    }

#pragma unroll
    for (int mt = 0; mt < 4; mt++) {
        const int mr0 = m0 + wm * 64 + mt * 16 + g;
        const int mr1 = mr0 + 8;
        const float s0 = E[mr0], s1 = E[mr1];
#pragma unroll
        for (int nt = 0; nt < 4; nt++) {
            const int nc = n0 + wn * 32 + nt * 8 + 2 * t;
            float2 v0 = make_float2(acc[mt][nt][0] * s0, acc[mt][nt][1] * s0);
            float2 v1 = make_float2(acc[mt][nt][2] * s1, acc[mt][nt][3] * s1);
            *reinterpret_cast<float2*>(&C[(size_t)mr0 * ldc + nc]) = v0;
            *reinterpret_cast<float2*>(&C[(size_t)mr1 * ldc + nc]) = v1;
        }
    }
}

__launch_bounds__(256, 2)
__global__ void hgemmB(const __half* __restrict__ adjH,
                       const __half* __restrict__ supH,
                       const float* __restrict__ degree,
                       float* __restrict__ out)
{
    extern __shared__ __align__(16) char smem[];
    const uint32_t sb = smem_u32(smem);
    const int n0 = blockIdx.x * BNb;
    if (blockIdx.y < (N_Uc / BMb)) {
        // GEMM2: out_u = deg_u * (adj @ sup_i)
        gemmB_body<true>(adjH, supH + (size_t)N_Uc * D_Hc, degree, out,
                         blockIdx.y * BMb, n0, sb);
    } else {
        // GEMM3: out_i = deg_i * (adj^T @ sup_u)
        gemmB_body<false>(adjH, supH, degree + N_Uc,
                          out + (size_t)N_Uc * D_Hc,
                          (blockIdx.y - N_Uc / BMb) * BMb, n0, sb);
    }
}

// ---------------- fp32 -> fp16 pre-pass ----------------
__global__ void f32_to_f16(const float* __restrict__ src, __half* __restrict__ dst) {
    size_t i = ((size_t)blockIdx.x * blockDim.x + threadIdx.x) * 8;
    float4 v0 = *reinterpret_cast<const float4*>(src + i);
    float4 v1 = *reinterpret_cast<const float4*>(src + i + 4);
    __half2 h0 = __floats2half2_rn(v0.x, v0.y);
    __half2 h1 = __floats2half2_rn(v0.z, v0.w);
    __half2 h2 = __floats2half2_rn(v1.x, v1.y);
    __half2 h3 = __floats2half2_rn(v1.z, v1.w);
    uint4 u;
    u.x = *reinterpret_cast<uint32_t*>(&h0);
    u.y = *reinterpret_cast<uint32_t*>(&h1);
    u.z = *reinterpret_cast<uint32_t*>(&h2);
    u.w = *reinterpret_cast<uint32_t*>(&h3);
    *reinterpret_cast<uint4*>(dst + i) = u;
}

// ---------------- launch ----------------
extern "C" void kernel_launch(void* const* d_in, const int* in_sizes, int n_in,
                              void* d_out, int out_size)
{
    const float* input  = (const float*)d_in[0];
    const float* adj    = (const float*)d_in[1];
    const float* degree = (const float*)d_in[2];
    const float* W      = (const float*)d_in[3];
    const float* b      = (const float*)d_in[4];
    float* out = (float*)d_out;

    __half *inputH, *WH, *adjH, *supH;
    cudaGetSymbolAddress((void**)&inputH, g_inputH);
    cudaGetSymbolAddress((void**)&WH, g_WH);
    cudaGetSymbolAddress((void**)&adjH, g_adjH);
    cudaGetSymbolAddress((void**)&supH, g_supH);

    cudaFuncSetAttribute(hgemmA, cudaFuncAttributeMaxDynamicSharedMemorySize, SMEM_A_TOTAL);
    cudaFuncSetAttribute(hgemmB, cudaFuncAttributeMaxDynamicSharedMemorySize, SMEM_B_TOTAL);

    // pre-passes: RN-round everything to fp16 once
    f32_to_f16<<<(size_t)N_TOTc * D_INc / (8 * 256), 256>>>(input, inputH);
    f32_to_f16<<<(size_t)D_Hc * D_INc / (8 * 256), 256>>>(W, WH);
    f32_to_f16<<<(size_t)N_Uc * N_Ic / (8 * 256), 256>>>(adj, adjH);

    // GEMM1: supH = rn( input @ W^T + b )
    {
        dim3 grid(D_Hc / BNa, N_TOTc / BMa);
        hgemmA<<<grid, 128, SMEM_A_TOTAL>>>(
            inputH, WH, b, supH, D_INc, D_INc, D_INc, D_Hc);
    }
    // GEMM2 + GEMM3 merged (one launch, one scheduling tail)
    {
        dim3 grid(D_Hc / BNb, (N_Uc + N_Ic) / BMb);   // (16, 128)
        hgemmB<<<grid, 256, SMEM_B_TOTAL>>>(adjH, supH, degree, out);
    }
}